// round 15
// baseline (speedup 1.0000x reference)
#include <cuda_runtime.h>
#include <cuda_fp16.h>

#define L 4096
#define C 64
#define NB 4
#define GUARD (66 * 4096)
#define LL (L * L)

// Guarded scratch for the stencils.
__device__ __align__(16) float  g_Mbuf[2 * GUARD + NB * LL];  // M (fp32)
__device__ __align__(16) __half g_Eh[2 * GUARD + NB * LL];    // E (fp16, unnormalized)
__device__ __align__(16) __half g_Sh[NB * LL];                // S (fp16)
__device__ __align__(16) __half g_bh[NB * C * L];             // b (fp16, [c][l])
__device__ __align__(16) __half g_fth[NB * L * C];            // f^T hi [x][c]
__device__ __align__(16) __half g_ftl[NB * L * C];            // f^T lo
__device__ __align__(16) __half g_bth[NB * L * C];            // b^T hi [x][c]
__device__ __align__(16) __half g_btl[NB * L * C];            // b^T lo
__device__ __align__(16) float  g_part[NB * 4 * C * L];       // split-K partials
__device__ float g_rinv[NB][L];

__global__ __launch_bounds__(256) void k_zero_guards() {
    const int i = blockIdx.x * 256 + threadIdx.x;   // < GUARD/4 = 67584
    float4 z = make_float4(0.f, 0.f, 0.f, 0.f);
    ((float4 *)g_Mbuf)[i] = z;
    ((float4 *)(g_Mbuf + GUARD + NB * LL))[i] = z;
    if (i < GUARD / 8) {
        uint4 zu = make_uint4(0u, 0u, 0u, 0u);
        ((uint4 *)g_Eh)[i] = zu;
        ((uint4 *)(g_Eh + GUARD + NB * LL))[i] = zu;
    }
}

// f,b -> transposed [x][c] fp16 hi/lo split (for K1 MMA).
// For b (z==1) ALSO emits the natural-layout fp16 copy g_bh (for K4).
__global__ __launch_bounds__(256) void k_prep_split(const float *__restrict__ fin,
                                                    const float *__restrict__ bin) {
    __shared__ float tile[64][72];
    const int bt = blockIdx.y;
    const int x0 = blockIdx.x << 6;
    const int z = blockIdx.z;
    const float *src = (z ? bin : fin) + bt * (C * L);
    __half *dh = (z ? g_bth : g_fth) + ((size_t)bt * L + x0) * 64;
    __half *dl = (z ? g_btl : g_ftl) + ((size_t)bt * L + x0) * 64;
    const int tid = threadIdx.x;
#pragma unroll
    for (int i = 0; i < 4; i++) {
        int idx = tid + (i << 8);
        int c = idx >> 4, x4 = idx & 15;
        *(float4 *)&tile[c][x4 << 2] =
            *(const float4 *)&src[c * L + x0 + (x4 << 2)];
    }
    __syncthreads();
#pragma unroll
    for (int i = 0; i < 2; i++) {
        int idx = tid + (i << 8);
        int xr = idx >> 3, g = idx & 7;
        __half hs[8], ls[8];
#pragma unroll
        for (int j = 0; j < 8; j++) {
            float v = tile[(g << 3) + j][xr];
            __half h = __float2half_rn(v);
            hs[j] = h;
            ls[j] = __float2half_rn(v - __half2float(h));
        }
        *(uint4 *)&dh[xr * 64 + (g << 3)] = *(uint4 *)hs;
        *(uint4 *)&dl[xr * 64 + (g << 3)] = *(uint4 *)ls;
    }
    if (z) {   // natural-layout fp16 b for K4
        __half *bh = g_bh + (size_t)bt * (C * L);
#pragma unroll
        for (int i = 0; i < 2; i++) {
            int idx = tid + (i << 8);
            int c = idx >> 3, g8 = idx & 7;
            __half hs[8];
#pragma unroll
            for (int j = 0; j < 8; j++)
                hs[j] = __float2half_rn(tile[c][(g8 << 3) + j]);
            *(uint4 *)&bh[c * L + x0 + (g8 << 3)] = *(uint4 *)hs;
        }
    }
}

// ---- fp32 shared-row tap (2-p variant): one M row serves up to 2 outputs ----
template <int DY, int J>
__device__ __forceinline__ void row32(const float *__restrict__ base, float mult,
                                      float eLo, float eHi, float acc[2][8]) {
    constexpr int KMIN = (J - 1 < 0) ? 0 : J - 1;
    constexpr int KMAX = (J + 1 > 1) ? 1 : J + 1;
    constexpr int DXMIN = J - KMAX;
    constexpr int DXMAX = J - KMIN;
    const float *p = base + DY * (64 * (L + 1)) + J * L;
    float f[16];   // element e -> f[e+4]
    if (DXMIN < 0) {
        float4 v = *(const float4 *)(p - 4);
        f[0] = v.x; f[1] = v.y; f[2] = v.z; f[3] = v.w;
    }
    {
        float4 v = *(const float4 *)p;
        f[4] = v.x; f[5] = v.y; f[6] = v.z; f[7] = v.w;
    }
    {
        float4 v = *(const float4 *)(p + 4);
        f[8] = v.x; f[9] = v.y; f[10] = v.z; f[11] = v.w;
    }
    if (DXMAX >= 1) {
        float4 v = *(const float4 *)(p + 8);
        f[12] = v.x; f[13] = v.y; f[14] = v.z; f[15] = v.w;
    }
#pragma unroll
    for (int k = KMIN; k <= KMAX; k++) {
        const int dx = J - k;
        const float m0 = (dx == -1) ? mult * eLo : mult;
        const float m7 = (dx == 1) ? mult * eHi : mult;
        acc[k][0] = fmaf(m0, f[4 + dx + 0], acc[k][0]);
#pragma unroll
        for (int i = 1; i < 7; i++)
            acc[k][i] = fmaf(mult, f[4 + dx + i], acc[k][i]);
        acc[k][7] = fmaf(m7, f[4 + dx + 7], acc[k][7]);
    }
}

// ---- fp16 shared-row tap (2-p variant) ----
template <int DY, int J>
__device__ __forceinline__ void row16(const __half *__restrict__ base, float mult,
                                      float eLo, float eHi, float acc[2][8]) {
    constexpr int KMIN = (J - 1 < 0) ? 0 : J - 1;
    constexpr int KMAX = (J + 1 > 1) ? 1 : J + 1;
    constexpr int DXMIN = J - KMAX;
    constexpr int DXMAX = J - KMIN;
    const __half *p = base + DY * (64 * (L + 1)) + J * L;
    unsigned u[12];
    if (DXMIN < 0) {
        uint4 v = *(const uint4 *)(p - 8);
        u[0] = v.x; u[1] = v.y; u[2] = v.z; u[3] = v.w;
    }
    {
        uint4 v = *(const uint4 *)p;
        u[4] = v.x; u[5] = v.y; u[6] = v.z; u[7] = v.w;
    }
    if (DXMAX >= 1) {
        uint4 v = *(const uint4 *)(p + 8);
        u[8] = v.x; u[9] = v.y; u[10] = v.z; u[11] = v.w;
    }
    float ff[12];
    if (DXMIN < 0) {
        float2 a = __half22float2(*(const __half2 *)&u[3]);
        ff[0] = a.x; ff[1] = a.y;
    }
#pragma unroll
    for (int w = 0; w < 4; w++) {
        float2 a = __half22float2(*(const __half2 *)&u[4 + w]);
        ff[2 + 2 * w] = a.x; ff[3 + 2 * w] = a.y;
    }
    if (DXMAX >= 1) {
        float2 a = __half22float2(*(const __half2 *)&u[8]);
        ff[10] = a.x; ff[11] = a.y;
    }
#pragma unroll
    for (int k = KMIN; k <= KMAX; k++) {
        const int dx = J - k;
        const float m0 = (dx == -1) ? mult * eLo : mult;
        const float m7 = (dx == 1) ? mult * eHi : mult;
        acc[k][0] = fmaf(m0, ff[2 + dx + 0], acc[k][0]);
#pragma unroll
        for (int i = 1; i < 7; i++)
            acc[k][i] = fmaf(mult, ff[2 + dx + i], acc[k][i]);
        acc[k][7] = fmaf(m7, ff[2 + dx + 7], acc[k][7]);
    }
}

// ---- shared MMA micro-pass for K1 ----
__device__ __forceinline__ void mma_pass(unsigned aBase, unsigned bBase,
                                         int warpP, int warpL, int lane,
                                         float acc[4][4][4]) {
    const int aRowL = lane & 15, aSel = lane >> 4;
    const int bRowBase = ((lane >> 4) << 3) + (lane & 7);
    const int bSel = (lane >> 3) & 1, swz = lane & 7;
#pragma unroll
    for (int k8 = 0; k8 < 4; k8++) {
        unsigned a[4][4];
#pragma unroll
        for (int mi = 0; mi < 4; mi++) {
            int row = warpP + (mi << 4) + aRowL;
            int phys = ((k8 << 1) + aSel) ^ (row & 7);
            unsigned addr = aBase + row * 128 + (phys << 4);
            asm volatile(
                "ldmatrix.sync.aligned.m8n8.x4.shared.b16 {%0,%1,%2,%3}, [%4];"
                : "=r"(a[mi][0]), "=r"(a[mi][1]), "=r"(a[mi][2]), "=r"(a[mi][3])
                : "r"(addr));
        }
        const int bPhys = ((k8 << 1) + bSel) ^ swz;
#pragma unroll
        for (int jp = 0; jp < 2; jp++) {
            unsigned b0, b1, b2, b3;
            unsigned addr = bBase + (warpL + (jp << 4) + bRowBase) * 128 + (bPhys << 4);
            asm volatile(
                "ldmatrix.sync.aligned.m8n8.x4.shared.b16 {%0,%1,%2,%3}, [%4];"
                : "=r"(b0), "=r"(b1), "=r"(b2), "=r"(b3) : "r"(addr));
#pragma unroll
            for (int mi = 0; mi < 4; mi++) {
                float *d0 = acc[mi][2 * jp];
                float *d1 = acc[mi][2 * jp + 1];
                asm volatile(
                    "mma.sync.aligned.m16n8k16.row.col.f32.f16.f16.f32 "
                    "{%0,%1,%2,%3}, {%4,%5,%6,%7}, {%8,%9}, {%0,%1,%2,%3};"
                    : "+f"(d0[0]), "+f"(d0[1]), "+f"(d0[2]), "+f"(d0[3])
                    : "r"(a[mi][0]), "r"(a[mi][1]), "r"(a[mi][2]), "r"(a[mi][3]),
                      "r"(b0), "r"(b1));
                asm volatile(
                    "mma.sync.aligned.m16n8k16.row.col.f32.f16.f16.f32 "
                    "{%0,%1,%2,%3}, {%4,%5,%6,%7}, {%8,%9}, {%0,%1,%2,%3};"
                    : "+f"(d1[0]), "+f"(d1[1]), "+f"(d1[2]), "+f"(d1[3])
                    : "r"(a[mi][0]), "r"(a[mi][1]), "r"(a[mi][2]), "r"(a[mi][3]),
                      "r"(b2), "r"(b3));
            }
        }
    }
}

// ============================================================
// K1 (tensor): M = fh*bh + fl*bh + fh*bl
// ============================================================
__global__ __launch_bounds__(256) void k_gemm_M_mma() {
    __shared__ __half Ah[128 * 64];
    __shared__ __half Al[128 * 64];
    __shared__ __half Bs[128 * 64];
    const int bt = blockIdx.z;
    const int p0 = blockIdx.y << 7;
    const int l0 = blockIdx.x << 7;
    const int tid = threadIdx.x;
    const int warp = tid >> 5, lane = tid & 31;
    const int warpP = (warp >> 2) << 6;
    const int warpL = (warp & 3) << 5;
    const __half *fh = g_fth + ((size_t)bt * L + p0) * 64;
    const __half *fl = g_ftl + ((size_t)bt * L + p0) * 64;
    const __half *bh = g_bth + ((size_t)bt * L + l0) * 64;
    const __half *bl = g_btl + ((size_t)bt * L + l0) * 64;

    unsigned aB = (unsigned)__cvta_generic_to_shared(Ah);
    unsigned lB = (unsigned)__cvta_generic_to_shared(Al);
    unsigned bB = (unsigned)__cvta_generic_to_shared(Bs);

    float acc[4][4][4];
#pragma unroll
    for (int i = 0; i < 4; i++)
#pragma unroll
        for (int j = 0; j < 4; j++)
#pragma unroll
            for (int k = 0; k < 4; k++) acc[i][j][k] = 0.f;

#pragma unroll
    for (int i = 0; i < 4; i++) {
        int idx = tid + (i << 8);
        int row = idx >> 3, g = idx & 7;
        int soff = row * 64 + ((g ^ (row & 7)) << 3);
        *(uint4 *)&Ah[soff] = *(const uint4 *)&fh[row * 64 + (g << 3)];
        *(uint4 *)&Al[soff] = *(const uint4 *)&fl[row * 64 + (g << 3)];
        *(uint4 *)&Bs[soff] = *(const uint4 *)&bh[row * 64 + (g << 3)];
    }
    __syncthreads();
    mma_pass(aB, bB, warpP, warpL, lane, acc);
    mma_pass(lB, bB, warpP, warpL, lane, acc);
    __syncthreads();
#pragma unroll
    for (int i = 0; i < 4; i++) {
        int idx = tid + (i << 8);
        int row = idx >> 3, g = idx & 7;
        *(uint4 *)&Bs[row * 64 + ((g ^ (row & 7)) << 3)] =
            *(const uint4 *)&bl[row * 64 + (g << 3)];
    }
    __syncthreads();
    mma_pass(aB, bB, warpP, warpL, lane, acc);

    float *out = g_Mbuf + GUARD + (size_t)bt * LL;
    const int mRow = lane >> 2, nCol = (lane & 3) << 1;
#pragma unroll
    for (int mi = 0; mi < 4; mi++) {
        const int r = p0 + warpP + (mi << 4) + mRow;
#pragma unroll
        for (int n8 = 0; n8 < 4; n8++) {
            const int cc = l0 + warpL + (n8 << 3) + nCol;
            float2 v0; v0.x = acc[mi][n8][0]; v0.y = acc[mi][n8][1];
            float2 v1; v1.x = acc[mi][n8][2]; v1.y = acc[mi][n8][3];
            *(float2 *)&out[(size_t)r * L + cc] = v0;
            *(float2 *)&out[(size_t)(r + 8) * L + cc] = v1;
        }
    }
}

// ============================================================
// K2: 2-p shared-row stencil + softmax; 512 threads, 1 chunk each.
// E fp16 (unnormalized) + rinv.
// ============================================================
__global__ __launch_bounds__(512) void k_score_softmax() {
    const int bt = blockIdx.y;
    const int g = blockIdx.x;            // 2048 groups of 2 p
    const int py = g >> 5;
    const int px0 = (g & 31) << 1;
    const int pbase = py * 64 + px0;
    const float *Mb = g_Mbuf + GUARD + (size_t)bt * LL + (size_t)pbase * L;
    const int t = threadIdx.x;           // 0..511, l = t*8
    __shared__ float2 redA[16], redB[16];

    float rowv[3], colv[4];
#pragma unroll
    for (int d = 0; d < 3; d++)
        rowv[d] = ((unsigned)(py + d - 1) < 64u) ? 1.f : 0.f;
#pragma unroll
    for (int j = 0; j < 4; j++)
        colv[j] = ((unsigned)(px0 + j - 1) < 64u) ? 1.f : 0.f;
    const float eLo = ((t & 7) == 0) ? 0.f : 1.f;
    const float eHi = ((t & 7) == 7) ? 0.f : 1.f;

    const int l = t << 3;
    const int ly = t >> 3;
    float ym[3];
    ym[0] = ((unsigned)(ly - 1) < 64u) ? 1.f : 0.f;
    ym[1] = 1.f;
    ym[2] = ((unsigned)(ly + 1) < 64u) ? 1.f : 0.f;

    float acc[2][8] = {};
    const float *base = Mb + l;
#define SROW(DYv, Jv) \
    row32<DYv, Jv>(base, rowv[DYv + 1] * colv[Jv + 1] * ym[DYv + 1], eLo, eHi, acc)
    SROW(-1, -1); SROW(-1, 0); SROW(-1, 1); SROW(-1, 2);
    SROW(0, -1);  SROW(0, 0);  SROW(0, 1);  SROW(0, 2);
    SROW(1, -1);  SROW(1, 0);  SROW(1, 1);  SROW(1, 2);
#undef SROW

    float2 mx;
    mx.x = acc[0][0]; mx.y = acc[1][0];
#pragma unroll
    for (int i = 1; i < 8; i++) {
        mx.x = fmaxf(mx.x, acc[0][i]);
        mx.y = fmaxf(mx.y, acc[1][i]);
    }
#pragma unroll
    for (int o = 16; o; o >>= 1) {
        mx.x = fmaxf(mx.x, __shfl_xor_sync(~0u, mx.x, o));
        mx.y = fmaxf(mx.y, __shfl_xor_sync(~0u, mx.y, o));
    }
    if ((t & 31) == 0) redA[t >> 5] = mx;
    __syncthreads();
    float2 rm = redA[0];
#pragma unroll
    for (int w = 1; w < 16; w++) {
        rm.x = fmaxf(rm.x, redA[w].x);
        rm.y = fmaxf(rm.y, redA[w].y);
    }

    float2 sm = make_float2(0.f, 0.f);
#pragma unroll
    for (int i = 0; i < 8; i++) {
        float e0 = __expf(10.f * (acc[0][i] - rm.x)); acc[0][i] = e0; sm.x += e0;
        float e1 = __expf(10.f * (acc[1][i] - rm.y)); acc[1][i] = e1; sm.y += e1;
    }
#pragma unroll
    for (int o = 16; o; o >>= 1) {
        sm.x += __shfl_xor_sync(~0u, sm.x, o);
        sm.y += __shfl_xor_sync(~0u, sm.y, o);
    }
    if ((t & 31) == 0) redB[t >> 5] = sm;
    __syncthreads();

    __half *E = g_Eh + GUARD + (size_t)bt * LL + (size_t)pbase * L;
#pragma unroll
    for (int k = 0; k < 2; k++) {
        __half2 h0 = __floats2half2_rn(acc[k][0], acc[k][1]);
        __half2 h1 = __floats2half2_rn(acc[k][2], acc[k][3]);
        __half2 h2 = __floats2half2_rn(acc[k][4], acc[k][5]);
        __half2 h3 = __floats2half2_rn(acc[k][6], acc[k][7]);
        uint4 u;
        u.x = *(unsigned *)&h0; u.y = *(unsigned *)&h1;
        u.z = *(unsigned *)&h2; u.w = *(unsigned *)&h3;
        *(uint4 *)&E[(size_t)k * L + l] = u;
    }

    if (t == 0) {
        float2 tt = redB[0];
#pragma unroll
        for (int w = 1; w < 16; w++) {
            tt.x += redB[w].x;
            tt.y += redB[w].y;
        }
        g_rinv[bt][pbase] = 1.f / tt.x;
        g_rinv[bt][pbase + 1] = 1.f / tt.y;
    }
}

// ============================================================
// K3: 2-p shared-row stencil; 512 threads, 1 chunk each.
// S fp16 = (1/9) sum E*rinv(source row)
// ============================================================
__global__ __launch_bounds__(512) void k_attn_S() {
    const int bt = blockIdx.y;
    const int g = blockIdx.x;            // 2048
    const int py = g >> 5;
    const int px0 = (g & 31) << 1;
    const int pbase = py * 64 + px0;
    const __half *Eb = g_Eh + GUARD + (size_t)bt * LL + (size_t)pbase * L;
    __half *Sb = g_Sh + (size_t)bt * LL + (size_t)pbase * L;
    const float *__restrict__ ri = g_rinv[bt];
    const int t = threadIdx.x;

    float rowm[3][4];
#pragma unroll
    for (int d = 0; d < 3; d++)
#pragma unroll
        for (int j = 0; j < 4; j++) {
            bool ok = ((unsigned)(py + d - 1) < 64u) &&
                      ((unsigned)(px0 + j - 1) < 64u);
            rowm[d][j] = ok ? ri[pbase + (d - 1) * 64 + (j - 1)] : 0.f;
        }
    const float eLo = ((t & 7) == 0) ? 0.f : 1.f;
    const float eHi = ((t & 7) == 7) ? 0.f : 1.f;

    const int l = t << 3;
    const int ly = t >> 3;
    float ym[3];
    ym[0] = ((unsigned)(ly - 1) < 64u) ? 1.f : 0.f;
    ym[1] = 1.f;
    ym[2] = ((unsigned)(ly + 1) < 64u) ? 1.f : 0.f;

    float acc[2][8] = {};
    const __half *base = Eb + l;
#define HROW(DYv, Jv) \
    row16<DYv, Jv>(base, rowm[DYv + 1][Jv + 1] * ym[DYv + 1], eLo, eHi, acc)
    HROW(-1, -1); HROW(-1, 0); HROW(-1, 1); HROW(-1, 2);
    HROW(0, -1);  HROW(0, 0);  HROW(0, 1);  HROW(0, 2);
    HROW(1, -1);  HROW(1, 0);  HROW(1, 1);  HROW(1, 2);
#undef HROW
#pragma unroll
    for (int k = 0; k < 2; k++) {
        __half2 h0 = __floats2half2_rn(acc[k][0] * (1.f / 9.f), acc[k][1] * (1.f / 9.f));
        __half2 h1 = __floats2half2_rn(acc[k][2] * (1.f / 9.f), acc[k][3] * (1.f / 9.f));
        __half2 h2 = __floats2half2_rn(acc[k][4] * (1.f / 9.f), acc[k][5] * (1.f / 9.f));
        __half2 h3 = __floats2half2_rn(acc[k][6] * (1.f / 9.f), acc[k][7] * (1.f / 9.f));
        uint4 u;
        u.x = *(unsigned *)&h0; u.y = *(unsigned *)&h1;
        u.z = *(unsigned *)&h2; u.w = *(unsigned *)&h3;
        *(uint4 *)&Sb[(size_t)k * L + l] = u;
    }
}

// ============================================================
// K4 (tensor): y[c,p] = sum_l b[c,l]*S[p,l]   (split-K = 2)
// ============================================================
__global__ __launch_bounds__(128) void k_gemm_y_mma() {
    __shared__ __half As[64 * 64];
    __shared__ __half Bs[128 * 64];
    const int bt = blockIdx.z;
    const int ks = blockIdx.y;           // 0..1
    const int p0 = blockIdx.x << 7;
    const int tid = threadIdx.x;
    const int warp = tid >> 5, lane = tid & 31;
    const __half *bh = g_bh + (size_t)bt * (C * L);
    const __half *Sb = g_Sh + (size_t)bt * LL;

    unsigned asB = (unsigned)__cvta_generic_to_shared(As);
    unsigned bsB = (unsigned)__cvta_generic_to_shared(Bs);

    float acc[16][4];
#pragma unroll
    for (int j = 0; j < 16; j++)
#pragma unroll
        for (int k = 0; k < 4; k++) acc[j][k] = 0.f;

    const int aRow = warp * 16 + (lane & 15);
    const int aSel = lane >> 4;
    const int bRowBase = ((lane >> 4) << 3) + (lane & 7);
    const int bSel = (lane >> 3) & 1;
    const int swz = lane & 7;

    const int lt0 = ks << 11;
    for (int lt = lt0; lt < lt0 + 2048; lt += 64) {
        __syncthreads();
#pragma unroll
        for (int i = 0; i < 4; i++) {
            int idx = tid + (i << 7);
            int row = idx >> 3, g = idx & 7;
            *(uint4 *)&As[row * 64 + ((g ^ (row & 7)) << 3)] =
                *(const uint4 *)&bh[row * L + lt + (g << 3)];
        }
#pragma unroll
        for (int i = 0; i < 8; i++) {
            int idx = tid + (i << 7);
            int row = idx >> 3, g = idx & 7;
            *(uint4 *)&Bs[row * 64 + ((g ^ (row & 7)) << 3)] =
                *(const uint4 *)&Sb[(size_t)(p0 + row) * L + lt + (g << 3)];
        }
        __syncthreads();
#pragma unroll
        for (int k8 = 0; k8 < 4; k8++) {
            unsigned a0, a1, a2, a3;
            {
                int phys = ((k8 << 1) + aSel) ^ (aRow & 7);
                unsigned addr = asB + aRow * 128 + (phys << 4);
                asm volatile(
                    "ldmatrix.sync.aligned.m8n8.x4.shared.b16 {%0,%1,%2,%3}, [%4];"
                    : "=r"(a0), "=r"(a1), "=r"(a2), "=r"(a3) : "r"(addr));
            }
            const int bPhys = ((k8 << 1) + bSel) ^ swz;
#pragma unroll
            for (int jp = 0; jp < 8; jp++) {
                unsigned b0, b1, b2, b3;
                unsigned addr = bsB + (jp * 16 + bRowBase) * 128 + (bPhys << 4);
                asm volatile(
                    "ldmatrix.sync.aligned.m8n8.x4.shared.b16 {%0,%1,%2,%3}, [%4];"
                    : "=r"(b0), "=r"(b1), "=r"(b2), "=r"(b3) : "r"(addr));
                float *d0 = acc[2 * jp];
                float *d1 = acc[2 * jp + 1];
                asm volatile(
                    "mma.sync.aligned.m16n8k16.row.col.f32.f16.f16.f32 "
                    "{%0,%1,%2,%3}, {%4,%5,%6,%7}, {%8,%9}, {%0,%1,%2,%3};"
                    : "+f"(d0[0]), "+f"(d0[1]), "+f"(d0[2]), "+f"(d0[3])
                    : "r"(a0), "r"(a1), "r"(a2), "r"(a3), "r"(b0), "r"(b1));
                asm volatile(
                    "mma.sync.aligned.m16n8k16.row.col.f32.f16.f16.f32 "
                    "{%0,%1,%2,%3}, {%4,%5,%6,%7}, {%8,%9}, {%0,%1,%2,%3};"
                    : "+f"(d1[0]), "+f"(d1[1]), "+f"(d1[2]), "+f"(d1[3])
                    : "r"(a0), "r"(a1), "r"(a2), "r"(a3), "r"(b2), "r"(b3));
            }
        }
    }
    float *part = g_part + (size_t)((bt << 1) + ks) * (C * L);
    const int cRow = warp * 16 + (lane >> 2);
#pragma unroll
    for (int j = 0; j < 16; j++) {
        const int pc = p0 + j * 8 + ((lane & 3) << 1);
        float2 v0; v0.x = acc[j][0]; v0.y = acc[j][1];
        float2 v1; v1.x = acc[j][2]; v1.y = acc[j][3];
        *(float2 *)&part[cRow * L + pc] = v0;
        *(float2 *)&part[(cRow + 8) * L + pc] = v1;
    }
}

// reduce the 2 split-K partials into y
__global__ __launch_bounds__(256) void k_reduce_y(float *__restrict__ yout) {
    const int i = blockIdx.x * 256 + threadIdx.x;
    const int p4 = i & 1023;
    const int c = (i >> 10) & 63;
    const int bt = i >> 16;
    const float4 *part = (const float4 *)g_part;
    float4 s = make_float4(0.f, 0.f, 0.f, 0.f);
#pragma unroll
    for (int ks = 0; ks < 2; ks++) {
        float4 v = part[((size_t)((bt << 1) + ks) * 64 + c) * 1024 + p4];
        s.x += v.x; s.y += v.y; s.z += v.z; s.w += v.w;
    }
    ((float4 *)yout)[(bt * 64 + c) * 1024 + p4] = s;
}

// ============================================================
// K5: w output
// ============================================================
__global__ __launch_bounds__(256) void k_wout(const float *__restrict__ bin,
                                              float *__restrict__ wout) {
    const int idx = blockIdx.x * 256 + threadIdx.x;
    const int j3 = idx % 9;
    const int c = (idx / 9) & 63;
    const int l = (idx / 576) & 4095;
    const int bt = idx / (576 * 4096);
    const int dy = j3 / 3 - 1, dx = j3 % 3 - 1;
    const int ly = l >> 6, lx = l & 63;
    float v = 0.f;
    if ((unsigned)(ly + dy) < 64u && (unsigned)(lx + dx) < 64u)
        v = bin[bt * (C * L) + c * L + l + dy * 64 + dx];
    wout[idx] = v;
}

extern "C" void kernel_launch(void *const *d_in, const int *in_sizes, int n_in,
                              void *d_out, int out_size) {
    const float *f = (const float *)d_in[0];
    const float *b = (const float *)d_in[1];
    float *out = (float *)d_out;

    k_zero_guards<<<GUARD / 4 / 256, 256>>>();
    k_prep_split<<<dim3(64, NB, 2), 256>>>(f, b);
    k_gemm_M_mma<<<dim3(32, 32, NB), 256>>>();
    k_score_softmax<<<dim3(2048, NB), 512>>>();
    k_attn_S<<<dim3(2048, NB), 512>>>();
    k_gemm_y_mma<<<dim3(32, 2, NB), 128>>>();
    k_reduce_y<<<1024, 256>>>(out);
    k_wout<<<(NB * L * C * 9) / 256, 256>>>(b, out + NB * C * L);
}

// round 16
// speedup vs baseline: 1.1531x; 1.1531x over previous
#include <cuda_runtime.h>
#include <cuda_fp16.h>

#define L 4096
#define C 64
#define NB 4
#define GUARD (66 * 4096)
#define LL (L * L)

// Guarded scratch for the stencils.  Guards are NEVER written by any kernel
// and __device__ globals are zero-initialized at module load, so they are
// deterministically zero on every call (no zeroing kernel needed).
__device__ __align__(16) float  g_Mbuf[2 * GUARD + NB * LL];  // M (fp32)
__device__ __align__(16) __half g_Eh[2 * GUARD + NB * LL];    // E (fp16, unnormalized)
__device__ __align__(16) __half g_Sh[NB * LL];                // S (fp16)
__device__ __align__(16) __half g_bh[NB * C * L];             // b (fp16, [c][l])
__device__ __align__(16) __half g_fth[NB * L * C];            // f^T hi [x][c]
__device__ __align__(16) __half g_ftl[NB * L * C];            // f^T lo
__device__ __align__(16) __half g_bth[NB * L * C];            // b^T hi [x][c]
__device__ __align__(16) __half g_btl[NB * L * C];            // b^T lo
__device__ __align__(16) float  g_part[NB * 4 * C * L];       // split-K partials
__device__ float g_rinv[NB][L];

// f,b -> transposed [x][c] fp16 hi/lo split (for K1 MMA).
// For b (z==1) ALSO emits the natural-layout fp16 copy g_bh (for K4).
__global__ __launch_bounds__(256) void k_prep_split(const float *__restrict__ fin,
                                                    const float *__restrict__ bin) {
    __shared__ float tile[64][72];
    const int bt = blockIdx.y;
    const int x0 = blockIdx.x << 6;
    const int z = blockIdx.z;
    const float *src = (z ? bin : fin) + bt * (C * L);
    __half *dh = (z ? g_bth : g_fth) + ((size_t)bt * L + x0) * 64;
    __half *dl = (z ? g_btl : g_ftl) + ((size_t)bt * L + x0) * 64;
    const int tid = threadIdx.x;
#pragma unroll
    for (int i = 0; i < 4; i++) {
        int idx = tid + (i << 8);
        int c = idx >> 4, x4 = idx & 15;
        *(float4 *)&tile[c][x4 << 2] =
            *(const float4 *)&src[c * L + x0 + (x4 << 2)];
    }
    __syncthreads();
#pragma unroll
    for (int i = 0; i < 2; i++) {
        int idx = tid + (i << 8);
        int xr = idx >> 3, g = idx & 7;
        __half hs[8], ls[8];
#pragma unroll
        for (int j = 0; j < 8; j++) {
            float v = tile[(g << 3) + j][xr];
            __half h = __float2half_rn(v);
            hs[j] = h;
            ls[j] = __float2half_rn(v - __half2float(h));
        }
        *(uint4 *)&dh[xr * 64 + (g << 3)] = *(uint4 *)hs;
        *(uint4 *)&dl[xr * 64 + (g << 3)] = *(uint4 *)ls;
    }
    if (z) {   // natural-layout fp16 b for K4
        __half *bh = g_bh + (size_t)bt * (C * L);
#pragma unroll
        for (int i = 0; i < 2; i++) {
            int idx = tid + (i << 8);
            int c = idx >> 3, g8 = idx & 7;
            __half hs[8];
#pragma unroll
            for (int j = 0; j < 8; j++)
                hs[j] = __float2half_rn(tile[c][(g8 << 3) + j]);
            *(uint4 *)&bh[c * L + x0 + (g8 << 3)] = *(uint4 *)hs;
        }
    }
}

// ---- fp32 shared-row tap (2-p variant): one M row serves up to 2 outputs ----
template <int DY, int J>
__device__ __forceinline__ void row32(const float *__restrict__ base, float mult,
                                      float eLo, float eHi, float acc[2][8]) {
    constexpr int KMIN = (J - 1 < 0) ? 0 : J - 1;
    constexpr int KMAX = (J + 1 > 1) ? 1 : J + 1;
    constexpr int DXMIN = J - KMAX;
    constexpr int DXMAX = J - KMIN;
    const float *p = base + DY * (64 * (L + 1)) + J * L;
    float f[16];   // element e -> f[e+4]
    if (DXMIN < 0) {
        float4 v = *(const float4 *)(p - 4);
        f[0] = v.x; f[1] = v.y; f[2] = v.z; f[3] = v.w;
    }
    {
        float4 v = *(const float4 *)p;
        f[4] = v.x; f[5] = v.y; f[6] = v.z; f[7] = v.w;
    }
    {
        float4 v = *(const float4 *)(p + 4);
        f[8] = v.x; f[9] = v.y; f[10] = v.z; f[11] = v.w;
    }
    if (DXMAX >= 1) {
        float4 v = *(const float4 *)(p + 8);
        f[12] = v.x; f[13] = v.y; f[14] = v.z; f[15] = v.w;
    }
#pragma unroll
    for (int k = KMIN; k <= KMAX; k++) {
        const int dx = J - k;
        const float m0 = (dx == -1) ? mult * eLo : mult;
        const float m7 = (dx == 1) ? mult * eHi : mult;
        acc[k][0] = fmaf(m0, f[4 + dx + 0], acc[k][0]);
#pragma unroll
        for (int i = 1; i < 7; i++)
            acc[k][i] = fmaf(mult, f[4 + dx + i], acc[k][i]);
        acc[k][7] = fmaf(m7, f[4 + dx + 7], acc[k][7]);
    }
}

// ---- fp16 shared-row tap (2-p variant) ----
template <int DY, int J>
__device__ __forceinline__ void row16(const __half *__restrict__ base, float mult,
                                      float eLo, float eHi, float acc[2][8]) {
    constexpr int KMIN = (J - 1 < 0) ? 0 : J - 1;
    constexpr int KMAX = (J + 1 > 1) ? 1 : J + 1;
    constexpr int DXMIN = J - KMAX;
    constexpr int DXMAX = J - KMIN;
    const __half *p = base + DY * (64 * (L + 1)) + J * L;
    unsigned u[12];
    if (DXMIN < 0) {
        uint4 v = *(const uint4 *)(p - 8);
        u[0] = v.x; u[1] = v.y; u[2] = v.z; u[3] = v.w;
    }
    {
        uint4 v = *(const uint4 *)p;
        u[4] = v.x; u[5] = v.y; u[6] = v.z; u[7] = v.w;
    }
    if (DXMAX >= 1) {
        uint4 v = *(const uint4 *)(p + 8);
        u[8] = v.x; u[9] = v.y; u[10] = v.z; u[11] = v.w;
    }
    float ff[12];
    if (DXMIN < 0) {
        float2 a = __half22float2(*(const __half2 *)&u[3]);
        ff[0] = a.x; ff[1] = a.y;
    }
#pragma unroll
    for (int w = 0; w < 4; w++) {
        float2 a = __half22float2(*(const __half2 *)&u[4 + w]);
        ff[2 + 2 * w] = a.x; ff[3 + 2 * w] = a.y;
    }
    if (DXMAX >= 1) {
        float2 a = __half22float2(*(const __half2 *)&u[8]);
        ff[10] = a.x; ff[11] = a.y;
    }
#pragma unroll
    for (int k = KMIN; k <= KMAX; k++) {
        const int dx = J - k;
        const float m0 = (dx == -1) ? mult * eLo : mult;
        const float m7 = (dx == 1) ? mult * eHi : mult;
        acc[k][0] = fmaf(m0, ff[2 + dx + 0], acc[k][0]);
#pragma unroll
        for (int i = 1; i < 7; i++)
            acc[k][i] = fmaf(mult, ff[2 + dx + i], acc[k][i]);
        acc[k][7] = fmaf(m7, ff[2 + dx + 7], acc[k][7]);
    }
}

// ---- shared MMA micro-pass for K1 ----
__device__ __forceinline__ void mma_pass(unsigned aBase, unsigned bBase,
                                         int warpP, int warpL, int lane,
                                         float acc[4][4][4]) {
    const int aRowL = lane & 15, aSel = lane >> 4;
    const int bRowBase = ((lane >> 4) << 3) + (lane & 7);
    const int bSel = (lane >> 3) & 1, swz = lane & 7;
#pragma unroll
    for (int k8 = 0; k8 < 4; k8++) {
        unsigned a[4][4];
#pragma unroll
        for (int mi = 0; mi < 4; mi++) {
            int row = warpP + (mi << 4) + aRowL;
            int phys = ((k8 << 1) + aSel) ^ (row & 7);
            unsigned addr = aBase + row * 128 + (phys << 4);
            asm volatile(
                "ldmatrix.sync.aligned.m8n8.x4.shared.b16 {%0,%1,%2,%3}, [%4];"
                : "=r"(a[mi][0]), "=r"(a[mi][1]), "=r"(a[mi][2]), "=r"(a[mi][3])
                : "r"(addr));
        }
        const int bPhys = ((k8 << 1) + bSel) ^ swz;
#pragma unroll
        for (int jp = 0; jp < 2; jp++) {
            unsigned b0, b1, b2, b3;
            unsigned addr = bBase + (warpL + (jp << 4) + bRowBase) * 128 + (bPhys << 4);
            asm volatile(
                "ldmatrix.sync.aligned.m8n8.x4.shared.b16 {%0,%1,%2,%3}, [%4];"
                : "=r"(b0), "=r"(b1), "=r"(b2), "=r"(b3) : "r"(addr));
#pragma unroll
            for (int mi = 0; mi < 4; mi++) {
                float *d0 = acc[mi][2 * jp];
                float *d1 = acc[mi][2 * jp + 1];
                asm volatile(
                    "mma.sync.aligned.m16n8k16.row.col.f32.f16.f16.f32 "
                    "{%0,%1,%2,%3}, {%4,%5,%6,%7}, {%8,%9}, {%0,%1,%2,%3};"
                    : "+f"(d0[0]), "+f"(d0[1]), "+f"(d0[2]), "+f"(d0[3])
                    : "r"(a[mi][0]), "r"(a[mi][1]), "r"(a[mi][2]), "r"(a[mi][3]),
                      "r"(b0), "r"(b1));
                asm volatile(
                    "mma.sync.aligned.m16n8k16.row.col.f32.f16.f16.f32 "
                    "{%0,%1,%2,%3}, {%4,%5,%6,%7}, {%8,%9}, {%0,%1,%2,%3};"
                    : "+f"(d1[0]), "+f"(d1[1]), "+f"(d1[2]), "+f"(d1[3])
                    : "r"(a[mi][0]), "r"(a[mi][1]), "r"(a[mi][2]), "r"(a[mi][3]),
                      "r"(b2), "r"(b3));
            }
        }
    }
}

// ============================================================
// K1 (tensor): M = fh*bh + fl*bh + fh*bl
// ============================================================
__global__ __launch_bounds__(256) void k_gemm_M_mma() {
    __shared__ __half Ah[128 * 64];
    __shared__ __half Al[128 * 64];
    __shared__ __half Bs[128 * 64];
    const int bt = blockIdx.z;
    const int p0 = blockIdx.y << 7;
    const int l0 = blockIdx.x << 7;
    const int tid = threadIdx.x;
    const int warp = tid >> 5, lane = tid & 31;
    const int warpP = (warp >> 2) << 6;
    const int warpL = (warp & 3) << 5;
    const __half *fh = g_fth + ((size_t)bt * L + p0) * 64;
    const __half *fl = g_ftl + ((size_t)bt * L + p0) * 64;
    const __half *bh = g_bth + ((size_t)bt * L + l0) * 64;
    const __half *bl = g_btl + ((size_t)bt * L + l0) * 64;

    unsigned aB = (unsigned)__cvta_generic_to_shared(Ah);
    unsigned lB = (unsigned)__cvta_generic_to_shared(Al);
    unsigned bB = (unsigned)__cvta_generic_to_shared(Bs);

    float acc[4][4][4];
#pragma unroll
    for (int i = 0; i < 4; i++)
#pragma unroll
        for (int j = 0; j < 4; j++)
#pragma unroll
            for (int k = 0; k < 4; k++) acc[i][j][k] = 0.f;

#pragma unroll
    for (int i = 0; i < 4; i++) {
        int idx = tid + (i << 8);
        int row = idx >> 3, g = idx & 7;
        int soff = row * 64 + ((g ^ (row & 7)) << 3);
        *(uint4 *)&Ah[soff] = *(const uint4 *)&fh[row * 64 + (g << 3)];
        *(uint4 *)&Al[soff] = *(const uint4 *)&fl[row * 64 + (g << 3)];
        *(uint4 *)&Bs[soff] = *(const uint4 *)&bh[row * 64 + (g << 3)];
    }
    __syncthreads();
    mma_pass(aB, bB, warpP, warpL, lane, acc);
    mma_pass(lB, bB, warpP, warpL, lane, acc);
    __syncthreads();
#pragma unroll
    for (int i = 0; i < 4; i++) {
        int idx = tid + (i << 8);
        int row = idx >> 3, g = idx & 7;
        *(uint4 *)&Bs[row * 64 + ((g ^ (row & 7)) << 3)] =
            *(const uint4 *)&bl[row * 64 + (g << 3)];
    }
    __syncthreads();
    mma_pass(aB, bB, warpP, warpL, lane, acc);

    float *out = g_Mbuf + GUARD + (size_t)bt * LL;
    const int mRow = lane >> 2, nCol = (lane & 3) << 1;
#pragma unroll
    for (int mi = 0; mi < 4; mi++) {
        const int r = p0 + warpP + (mi << 4) + mRow;
#pragma unroll
        for (int n8 = 0; n8 < 4; n8++) {
            const int cc = l0 + warpL + (n8 << 3) + nCol;
            float2 v0; v0.x = acc[mi][n8][0]; v0.y = acc[mi][n8][1];
            float2 v1; v1.x = acc[mi][n8][2]; v1.y = acc[mi][n8][3];
            *(float2 *)&out[(size_t)r * L + cc] = v0;
            *(float2 *)&out[(size_t)(r + 8) * L + cc] = v1;
        }
    }
}

// ============================================================
// K2: 2-p shared-row stencil + softmax; 256 threads, 2 chunks each.
// E fp16 (unnormalized) + rinv.
// ============================================================
__global__ __launch_bounds__(256) void k_score_softmax() {
    const int bt = blockIdx.y;
    const int g = blockIdx.x;            // 2048 groups of 2 p
    const int py = g >> 5;
    const int px0 = (g & 31) << 1;
    const int pbase = py * 64 + px0;
    const float *Mb = g_Mbuf + GUARD + (size_t)bt * LL + (size_t)pbase * L;
    const int t = threadIdx.x;
    __shared__ float2 redA[8], redB[8];

    float rowv[3], colv[4];
#pragma unroll
    for (int d = 0; d < 3; d++)
        rowv[d] = ((unsigned)(py + d - 1) < 64u) ? 1.f : 0.f;
#pragma unroll
    for (int j = 0; j < 4; j++)
        colv[j] = ((unsigned)(px0 + j - 1) < 64u) ? 1.f : 0.f;
    const float eLo = ((t & 7) == 0) ? 0.f : 1.f;
    const float eHi = ((t & 7) == 7) ? 0.f : 1.f;

    float s[2][16];
#pragma unroll
    for (int jg = 0; jg < 2; jg++) {
        const int gidx = (jg << 8) + t;
        const int l = gidx << 3;
        const int ly = gidx >> 3;
        float ym[3];
        ym[0] = ((unsigned)(ly - 1) < 64u) ? 1.f : 0.f;
        ym[1] = 1.f;
        ym[2] = ((unsigned)(ly + 1) < 64u) ? 1.f : 0.f;
        float acc[2][8] = {};
        const float *base = Mb + l;
#define SROW(DYv, Jv) \
        row32<DYv, Jv>(base, rowv[DYv + 1] * colv[Jv + 1] * ym[DYv + 1], eLo, eHi, acc)
        SROW(-1, -1); SROW(-1, 0); SROW(-1, 1); SROW(-1, 2);
        SROW(0, -1);  SROW(0, 0);  SROW(0, 1);  SROW(0, 2);
        SROW(1, -1);  SROW(1, 0);  SROW(1, 1);  SROW(1, 2);
#undef SROW
#pragma unroll
        for (int k = 0; k < 2; k++)
#pragma unroll
            for (int i = 0; i < 8; i++) s[k][jg * 8 + i] = acc[k][i];
    }

    float2 mx;
    mx.x = s[0][0]; mx.y = s[1][0];
#pragma unroll
    for (int i = 1; i < 16; i++) {
        mx.x = fmaxf(mx.x, s[0][i]);
        mx.y = fmaxf(mx.y, s[1][i]);
    }
#pragma unroll
    for (int o = 16; o; o >>= 1) {
        mx.x = fmaxf(mx.x, __shfl_xor_sync(~0u, mx.x, o));
        mx.y = fmaxf(mx.y, __shfl_xor_sync(~0u, mx.y, o));
    }
    if ((t & 31) == 0) redA[t >> 5] = mx;
    __syncthreads();
    float2 rm = redA[0];
#pragma unroll
    for (int w = 1; w < 8; w++) {
        rm.x = fmaxf(rm.x, redA[w].x);
        rm.y = fmaxf(rm.y, redA[w].y);
    }

    float2 sm = make_float2(0.f, 0.f);
#pragma unroll
    for (int i = 0; i < 16; i++) {
        float e0 = __expf(10.f * (s[0][i] - rm.x)); s[0][i] = e0; sm.x += e0;
        float e1 = __expf(10.f * (s[1][i] - rm.y)); s[1][i] = e1; sm.y += e1;
    }
#pragma unroll
    for (int o = 16; o; o >>= 1) {
        sm.x += __shfl_xor_sync(~0u, sm.x, o);
        sm.y += __shfl_xor_sync(~0u, sm.y, o);
    }
    if ((t & 31) == 0) redB[t >> 5] = sm;
    __syncthreads();

    __half *E = g_Eh + GUARD + (size_t)bt * LL + (size_t)pbase * L;
#pragma unroll
    for (int jg = 0; jg < 2; jg++) {
        const int l = ((jg << 8) + t) << 3;
#pragma unroll
        for (int k = 0; k < 2; k++) {
            __half2 h0 = __floats2half2_rn(s[k][jg * 8 + 0], s[k][jg * 8 + 1]);
            __half2 h1 = __floats2half2_rn(s[k][jg * 8 + 2], s[k][jg * 8 + 3]);
            __half2 h2 = __floats2half2_rn(s[k][jg * 8 + 4], s[k][jg * 8 + 5]);
            __half2 h3 = __floats2half2_rn(s[k][jg * 8 + 6], s[k][jg * 8 + 7]);
            uint4 u;
            u.x = *(unsigned *)&h0; u.y = *(unsigned *)&h1;
            u.z = *(unsigned *)&h2; u.w = *(unsigned *)&h3;
            *(uint4 *)&E[(size_t)k * L + l] = u;
        }
    }

    if (t == 0) {
        float2 tt = redB[0];
#pragma unroll
        for (int w = 1; w < 8; w++) {
            tt.x += redB[w].x;
            tt.y += redB[w].y;
        }
        g_rinv[bt][pbase] = 1.f / tt.x;
        g_rinv[bt][pbase + 1] = 1.f / tt.y;
    }
}

// ============================================================
// K3: 2-p shared-row stencil; 256 threads, 2 chunks each.
// S fp16 = (1/9) sum E*rinv(source row)
// ============================================================
__global__ __launch_bounds__(256) void k_attn_S() {
    const int bt = blockIdx.y;
    const int g = blockIdx.x;            // 2048
    const int py = g >> 5;
    const int px0 = (g & 31) << 1;
    const int pbase = py * 64 + px0;
    const __half *Eb = g_Eh + GUARD + (size_t)bt * LL + (size_t)pbase * L;
    __half *Sb = g_Sh + (size_t)bt * LL + (size_t)pbase * L;
    const float *__restrict__ ri = g_rinv[bt];
    const int t = threadIdx.x;

    float rowm[3][4];
#pragma unroll
    for (int d = 0; d < 3; d++)
#pragma unroll
        for (int j = 0; j < 4; j++) {
            bool ok = ((unsigned)(py + d - 1) < 64u) &&
                      ((unsigned)(px0 + j - 1) < 64u);
            rowm[d][j] = ok ? ri[pbase + (d - 1) * 64 + (j - 1)] : 0.f;
        }
    const float eLo = ((t & 7) == 0) ? 0.f : 1.f;
    const float eHi = ((t & 7) == 7) ? 0.f : 1.f;

#pragma unroll
    for (int jg = 0; jg < 2; jg++) {
        const int gidx = (jg << 8) + t;
        const int l = gidx << 3;
        const int ly = gidx >> 3;
        float ym[3];
        ym[0] = ((unsigned)(ly - 1) < 64u) ? 1.f : 0.f;
        ym[1] = 1.f;
        ym[2] = ((unsigned)(ly + 1) < 64u) ? 1.f : 0.f;
        float acc[2][8] = {};
        const __half *base = Eb + l;
#define HROW(DYv, Jv) \
        row16<DYv, Jv>(base, rowm[DYv + 1][Jv + 1] * ym[DYv + 1], eLo, eHi, acc)
        HROW(-1, -1); HROW(-1, 0); HROW(-1, 1); HROW(-1, 2);
        HROW(0, -1);  HROW(0, 0);  HROW(0, 1);  HROW(0, 2);
        HROW(1, -1);  HROW(1, 0);  HROW(1, 1);  HROW(1, 2);
#undef HROW
#pragma unroll
        for (int k = 0; k < 2; k++) {
            __half2 h0 = __floats2half2_rn(acc[k][0] * (1.f / 9.f), acc[k][1] * (1.f / 9.f));
            __half2 h1 = __floats2half2_rn(acc[k][2] * (1.f / 9.f), acc[k][3] * (1.f / 9.f));
            __half2 h2 = __floats2half2_rn(acc[k][4] * (1.f / 9.f), acc[k][5] * (1.f / 9.f));
            __half2 h3 = __floats2half2_rn(acc[k][6] * (1.f / 9.f), acc[k][7] * (1.f / 9.f));
            uint4 u;
            u.x = *(unsigned *)&h0; u.y = *(unsigned *)&h1;
            u.z = *(unsigned *)&h2; u.w = *(unsigned *)&h3;
            *(uint4 *)&Sb[(size_t)k * L + l] = u;
        }
    }
}

// ============================================================
// K4 (tensor): y[c,p] = sum_l b[c,l]*S[p,l]   (split-K = 4)
// ============================================================
__global__ __launch_bounds__(128) void k_gemm_y_mma() {
    __shared__ __half As[64 * 64];
    __shared__ __half Bs[128 * 64];
    const int bt = blockIdx.z;
    const int ks = blockIdx.y;
    const int p0 = blockIdx.x << 7;
    const int tid = threadIdx.x;
    const int warp = tid >> 5, lane = tid & 31;
    const __half *bh = g_bh + (size_t)bt * (C * L);
    const __half *Sb = g_Sh + (size_t)bt * LL;

    unsigned asB = (unsigned)__cvta_generic_to_shared(As);
    unsigned bsB = (unsigned)__cvta_generic_to_shared(Bs);

    float acc[16][4];
#pragma unroll
    for (int j = 0; j < 16; j++)
#pragma unroll
        for (int k = 0; k < 4; k++) acc[j][k] = 0.f;

    const int aRow = warp * 16 + (lane & 15);
    const int aSel = lane >> 4;
    const int bRowBase = ((lane >> 4) << 3) + (lane & 7);
    const int bSel = (lane >> 3) & 1;
    const int swz = lane & 7;

    const int lt0 = ks << 10;
    for (int lt = lt0; lt < lt0 + 1024; lt += 64) {
        __syncthreads();
#pragma unroll
        for (int i = 0; i < 4; i++) {
            int idx = tid + (i << 7);
            int row = idx >> 3, g = idx & 7;
            *(uint4 *)&As[row * 64 + ((g ^ (row & 7)) << 3)] =
                *(const uint4 *)&bh[row * L + lt + (g << 3)];
        }
#pragma unroll
        for (int i = 0; i < 8; i++) {
            int idx = tid + (i << 7);
            int row = idx >> 3, g = idx & 7;
            *(uint4 *)&Bs[row * 64 + ((g ^ (row & 7)) << 3)] =
                *(const uint4 *)&Sb[(size_t)(p0 + row) * L + lt + (g << 3)];
        }
        __syncthreads();
#pragma unroll
        for (int k8 = 0; k8 < 4; k8++) {
            unsigned a0, a1, a2, a3;
            {
                int phys = ((k8 << 1) + aSel) ^ (aRow & 7);
                unsigned addr = asB + aRow * 128 + (phys << 4);
                asm volatile(
                    "ldmatrix.sync.aligned.m8n8.x4.shared.b16 {%0,%1,%2,%3}, [%4];"
                    : "=r"(a0), "=r"(a1), "=r"(a2), "=r"(a3) : "r"(addr));
            }
            const int bPhys = ((k8 << 1) + bSel) ^ swz;
#pragma unroll
            for (int jp = 0; jp < 8; jp++) {
                unsigned b0, b1, b2, b3;
                unsigned addr = bsB + (jp * 16 + bRowBase) * 128 + (bPhys << 4);
                asm volatile(
                    "ldmatrix.sync.aligned.m8n8.x4.shared.b16 {%0,%1,%2,%3}, [%4];"
                    : "=r"(b0), "=r"(b1), "=r"(b2), "=r"(b3) : "r"(addr));
                float *d0 = acc[2 * jp];
                float *d1 = acc[2 * jp + 1];
                asm volatile(
                    "mma.sync.aligned.m16n8k16.row.col.f32.f16.f16.f32 "
                    "{%0,%1,%2,%3}, {%4,%5,%6,%7}, {%8,%9}, {%0,%1,%2,%3};"
                    : "+f"(d0[0]), "+f"(d0[1]), "+f"(d0[2]), "+f"(d0[3])
                    : "r"(a0), "r"(a1), "r"(a2), "r"(a3), "r"(b0), "r"(b1));
                asm volatile(
                    "mma.sync.aligned.m16n8k16.row.col.f32.f16.f16.f32 "
                    "{%0,%1,%2,%3}, {%4,%5,%6,%7}, {%8,%9}, {%0,%1,%2,%3};"
                    : "+f"(d1[0]), "+f"(d1[1]), "+f"(d1[2]), "+f"(d1[3])
                    : "r"(a0), "r"(a1), "r"(a2), "r"(a3), "r"(b2), "r"(b3));
            }
        }
    }
    float *part = g_part + (size_t)((bt << 2) + ks) * (C * L);
    const int cRow = warp * 16 + (lane >> 2);
#pragma unroll
    for (int j = 0; j < 16; j++) {
        const int pc = p0 + j * 8 + ((lane & 3) << 1);
        float2 v0; v0.x = acc[j][0]; v0.y = acc[j][1];
        float2 v1; v1.x = acc[j][2]; v1.y = acc[j][3];
        *(float2 *)&part[cRow * L + pc] = v0;
        *(float2 *)&part[(cRow + 8) * L + pc] = v1;
    }
}

// reduce the 4 split-K partials into y
__global__ __launch_bounds__(256) void k_reduce_y(float *__restrict__ yout) {
    const int i = blockIdx.x * 256 + threadIdx.x;
    const int p4 = i & 1023;
    const int c = (i >> 10) & 63;
    const int bt = i >> 16;
    const float4 *part = (const float4 *)g_part;
    float4 s = make_float4(0.f, 0.f, 0.f, 0.f);
#pragma unroll
    for (int ks = 0; ks < 4; ks++) {
        float4 v = part[((size_t)((bt << 2) + ks) * 64 + c) * 1024 + p4];
        s.x += v.x; s.y += v.y; s.z += v.z; s.w += v.w;
    }
    ((float4 *)yout)[(bt * 64 + c) * 1024 + p4] = s;
}

// ============================================================
// K5: w output
// ============================================================
__global__ __launch_bounds__(256) void k_wout(const float *__restrict__ bin,
                                              float *__restrict__ wout) {
    const int idx = blockIdx.x * 256 + threadIdx.x;
    const int j3 = idx % 9;
    const int c = (idx / 9) & 63;
    const int l = (idx / 576) & 4095;
    const int bt = idx / (576 * 4096);
    const int dy = j3 / 3 - 1, dx = j3 % 3 - 1;
    const int ly = l >> 6, lx = l & 63;
    float v = 0.f;
    if ((unsigned)(ly + dy) < 64u && (unsigned)(lx + dx) < 64u)
        v = bin[bt * (C * L) + c * L + l + dy * 64 + dx];
    wout[idx] = v;
}

extern "C" void kernel_launch(void *const *d_in, const int *in_sizes, int n_in,
                              void *d_out, int out_size) {
    const float *f = (const float *)d_in[0];
    const float *b = (const float *)d_in[1];
    float *out = (float *)d_out;

    k_prep_split<<<dim3(64, NB, 2), 256>>>(f, b);
    k_gemm_M_mma<<<dim3(32, 32, NB), 256>>>();
    k_score_softmax<<<dim3(2048, NB), 256>>>();
    k_attn_S<<<dim3(2048, NB), 256>>>();
    k_gemm_y_mma<<<dim3(32, 4, NB), 128>>>();
    k_reduce_y<<<1024, 256>>>(out);
    k_wout<<<(NB * L * C * 9) / 256, 256>>>(b, out + NB * C * L);
}